// round 10
// baseline (speedup 1.0000x reference)
#include <cuda_runtime.h>
#include <cstdint>

#define MAXDISP 192
#define HH      192
#define WW      384
#define WD      (WW + MAXDISP - 1)   /* 575 */
#define HW      (HH * WW)            /* 73728 */

#define NCHUNK 4                     /* D-chunks per view (warps = view x chunk) */
#define DPC    (MAXDISP / NCHUNK)    /* 48 disparities per chunk */
#define PIX    32                    /* pixels per block */
#define STG    6                     /* cp.async pipeline depth */

// v layout: [1][4][D][H][WD]  ch 0 = logits, ch 1..3 = color
// out layout: color_1[3*HW] | color_2[3*HW] | disp_1[HW] | disp_2[HW]

__device__ __forceinline__ void cpa4(uint32_t dst, const float* src) {
    asm volatile("cp.async.ca.shared.global [%0], [%1], 4;" :: "r"(dst), "l"(src));
}
__device__ __forceinline__ void cpa_commit() {
    asm volatile("cp.async.commit_group;" ::: "memory");
}
__device__ __forceinline__ void cpa_wait() {
    asm volatile("cp.async.wait_group %0;" :: "n"(STG - 1) : "memory");
}

__global__ __launch_bounds__(256, 7)
void volume_render_v6_kernel(const float* __restrict__ v, float* __restrict__ out) {
    const int lane  = threadIdx.x & 31;
    const int warp  = threadIdx.x >> 5;
    const int view  = warp & 1;          // 0: col=w, 1: col=w+shift
    const int chunk = warp >> 1;         // 0..3

    const int pix0 = blockIdx.x * PIX;
    const int h    = pix0 / WW;
    const int w0   = pix0 % WW;

    const int stride_d = HH * WD;            // 110400
    const int stride_c = MAXDISP * HH * WD;  // 21196800

    const int d0   = chunk * DPC;
    const int sh0  = view ? (MAXDISP - 1 - d0) : 0;   // initial column shift
    const int step = stride_d - view;                 // view2 shift shrinks per d

    // issue pointer (advances per issued stage)
    const float* pld = v + d0 * stride_d + h * WD + w0 + lane + sh0;

    // pipeline buffer: [warp][stage][ch][lane]  -> 8*6*4*32*4 = 24 KB
    __shared__ float pipe[8][STG][4][PIX];
    // per-lane shared base address for this warp's stage 0, this lane
    const uint32_t sbase =
        (uint32_t)__cvta_generic_to_shared(&pipe[warp][0][0][lane]);
    const uint32_t stg_stride = 4 * PIX * 4;   // 512B per stage
    const uint32_t ch_stride  = PIX * 4;       // 128B per channel

    // prologue: issue stages 0..STG-2 (STG-1 groups in flight)
    #pragma unroll
    for (int s = 0; s < STG - 1; ++s) {
        const uint32_t dstg = sbase + s * stg_stride;
        cpa4(dstg,                 pld);
        cpa4(dstg + ch_stride,     pld + stride_c);
        cpa4(dstg + 2 * ch_stride, pld + 2 * stride_c);
        cpa4(dstg + 3 * ch_stride, pld + 3 * stride_c);
        cpa_commit();
        pld += step;
    }

    float l = 0.f, ad = 0.f, ac0 = 0.f, ac1 = 0.f, ac2 = 0.f;
    float dv = (float)(MAXDISP - 1 - d0);    // disparity value = D-1-d

    int cslot = 0;            // compute slot
    int islot = STG - 1;      // issue slot

    for (int i = 0; i < DPC; ++i) {
        // issue stage i+STG-1 (keeps STG-1 stages in flight during compute)
        if (i + STG - 1 < DPC) {
            const uint32_t dstg = sbase + islot * stg_stride;
            cpa4(dstg,                 pld);
            cpa4(dstg + ch_stride,     pld + stride_c);
            cpa4(dstg + 2 * ch_stride, pld + 2 * stride_c);
            cpa4(dstg + 3 * ch_stride, pld + 3 * stride_c);
            pld += step;
        }
        cpa_commit();             // one group per iteration (possibly empty)
        cpa_wait();               // stage i complete (own-lane data -> no barrier)

        const float b  = pipe[warp][cslot][0][lane];
        const float q0 = pipe[warp][cslot][1][lane];
        const float q1 = pipe[warp][cslot][2][lane];
        const float q2 = pipe[warp][cslot][3][lane];

        // no max-subtraction: logits ~ N(0,1); exp cannot overflow fp32 and the
        // softmax ratio is shift-invariant; partials are linear -> splittable.
        const float e = __expf(b);

        l   += e;
        ad   = fmaf(e, dv, ad);
        ac0  = fmaf(e, q0, ac0);
        ac1  = fmaf(e, q1, ac1);
        ac2  = fmaf(e, q2, ac2);

        dv -= 1.0f;
        if (++cslot == STG) cslot = 0;
        if (++islot == STG) islot = 0;
    }

    // warp index = chunk*2 + view ; 8 warps x 5 values x 32 px = 5 KB
    __shared__ float red[2 * NCHUNK][5][PIX];
    red[warp][0][lane] = l;
    red[warp][1][lane] = ad;
    red[warp][2][lane] = ac0;
    red[warp][3][lane] = ac1;
    red[warp][4][lane] = ac2;
    __syncthreads();

    // reduce over chunks: fin[view][val][px], 320 tasks over 256 threads
    __shared__ float fin[2][5][PIX];
    for (int t = threadIdx.x; t < 2 * 5 * PIX; t += 256) {
        const int vw  = t / (5 * PIX);
        const int val = (t / PIX) % 5;
        const int px  = t & 31;
        float s = 0.f;
        #pragma unroll
        for (int cc = 0; cc < NCHUNK; ++cc) s += red[cc * 2 + vw][val][px];
        fin[vw][val][px] = s;
    }
    __syncthreads();

    // 8 outputs x 32 px = 256 tasks, one per thread
    // outv 0-2: color_1 ; 3-5: color_2 ; 6: disp_1 ; 7: disp_2
    const int outv = threadIdx.x >> 5;
    const int px   = threadIdx.x & 31;
    const int vw   = (outv < 3) ? 0 : (outv < 6 ? 1 : (outv - 6));
    const int val  = (outv < 6) ? (2 + outv - vw * 3) : 1;

    const float a = fin[vw][val][px];
    const float s = fin[vw][0][px];
    out[outv * HW + pix0 + px] = a / s;
}

extern "C" void kernel_launch(void* const* d_in, const int* in_sizes, int n_in,
                              void* d_out, int out_size) {
    const float* v = (const float*)d_in[0];
    float* out = (float*)d_out;

    const int blocks = HW / PIX;   // 2304
    volume_render_v6_kernel<<<blocks, 256>>>(v, out);
}

// round 11
// speedup vs baseline: 1.3514x; 1.3514x over previous
#include <cuda_runtime.h>

#define MAXDISP 192
#define HH      192
#define WW      384
#define WD      (WW + MAXDISP - 1)   /* 575 */
#define HW      (HH * WW)            /* 73728 */

#define NCHUNK 4                     /* D-chunks per view (warps = view x chunk) */
#define DPC    (MAXDISP / NCHUNK)    /* 48 disparities per chunk */
#define PIXB   64                    /* pixels per block: lane and lane+32 */

// v layout: [1][4][D][H][WD]  ch 0 = logits, ch 1..3 = color
// out layout: color_1[3*HW] | color_2[3*HW] | disp_1[HW] | disp_2[HW]
// per-warp accumulators (per pixel): 0:l 1:a_d 2..4:a_c

__global__ __launch_bounds__(256, 6)
void volume_render_v7_kernel(const float* __restrict__ v, float* __restrict__ out) {
    const int lane  = threadIdx.x & 31;
    const int warp  = threadIdx.x >> 5;
    const int view  = warp & 1;          // 0: col=w, 1: col=w+shift
    const int chunk = warp >> 1;         // 0..3

    const int pix0 = blockIdx.x * PIXB;  // 384 % 64 == 0 -> block stays in one row
    const int h    = pix0 / WW;
    const int w0   = pix0 % WW;

    const int stride_d = HH * WD;            // 110400
    const int stride_c = MAXDISP * HH * WD;  // 21196800

    const int d0   = chunk * DPC;
    const int sh0  = view ? (MAXDISP - 1 - d0) : 0;   // initial column shift
    const int step = stride_d - view;                 // view2 shift shrinks per d

    // pixel A = w0+lane, pixel B = w0+lane+32 -> 256B contiguous per stream
    const float* __restrict__ p = v + d0 * stride_d + h * WD + w0 + lane + sh0;

    float lA = 0.f, adA = 0.f, a0A = 0.f, a1A = 0.f, a2A = 0.f;
    float lB = 0.f, adB = 0.f, a0B = 0.f, a1B = 0.f, a2B = 0.f;
    float dv = (float)(MAXDISP - 1 - d0);    // disparity value = D-1-d

    #pragma unroll 4
    for (int i = 0; i < DPC; ++i) {
        // 8 independent loads: 4 streams x 2 adjacent 128B lines
        const float bA  = p[0];
        const float bB  = p[32];
        const float q0A = p[stride_c];
        const float q0B = p[stride_c + 32];
        const float q1A = p[2 * stride_c];
        const float q1B = p[2 * stride_c + 32];
        const float q2A = p[3 * stride_c];
        const float q2B = p[3 * stride_c + 32];

        // no max-subtraction: logits ~ N(0,1); exp cannot overflow fp32 and the
        // softmax ratio is shift-invariant; partials are linear -> splittable.
        const float eA = __expf(bA);
        const float eB = __expf(bB);

        lA  += eA;                      lB  += eB;
        adA  = fmaf(eA, dv,  adA);      adB  = fmaf(eB, dv,  adB);
        a0A  = fmaf(eA, q0A, a0A);      a0B  = fmaf(eB, q0B, a0B);
        a1A  = fmaf(eA, q1A, a1A);      a1B  = fmaf(eB, q1B, a1B);
        a2A  = fmaf(eA, q2A, a2A);      a2B  = fmaf(eB, q2B, a2B);

        p  += step;
        dv -= 1.0f;
    }

    // warp index = chunk*2 + view ; 8 warps x 5 values x 64 px = 10 KB
    __shared__ float red[2 * NCHUNK][5][PIXB];
    red[warp][0][lane] = lA;   red[warp][0][lane + 32] = lB;
    red[warp][1][lane] = adA;  red[warp][1][lane + 32] = adB;
    red[warp][2][lane] = a0A;  red[warp][2][lane + 32] = a0B;
    red[warp][3][lane] = a1A;  red[warp][3][lane + 32] = a1B;
    red[warp][4][lane] = a2A;  red[warp][4][lane + 32] = a2B;
    __syncthreads();

    // reduce over chunks: fin[view][val][px], 640 tasks over 256 threads
    __shared__ float fin[2][5][PIXB];
    for (int t = threadIdx.x; t < 2 * 5 * PIXB; t += 256) {
        const int vw  = t / (5 * PIXB);
        const int val = (t / PIXB) % 5;
        const int px  = t & 63;
        float s = 0.f;
        #pragma unroll
        for (int cc = 0; cc < NCHUNK; ++cc) s += red[cc * 2 + vw][val][px];
        fin[vw][val][px] = s;
    }
    __syncthreads();

    // 8 outputs x 64 px = 512 tasks over 256 threads
    // outv 0-2: color_1 ; 3-5: color_2 ; 6: disp_1 ; 7: disp_2
    for (int t = threadIdx.x; t < 8 * PIXB; t += 256) {
        const int outv = t >> 6;
        const int px   = t & 63;
        const int vw   = (outv < 3) ? 0 : (outv < 6 ? 1 : (outv - 6));
        const int val  = (outv < 6) ? (2 + outv - vw * 3) : 1;
        out[outv * HW + pix0 + px] = fin[vw][val][px] / fin[vw][0][px];
    }
}

extern "C" void kernel_launch(void* const* d_in, const int* in_sizes, int n_in,
                              void* d_out, int out_size) {
    const float* v = (const float*)d_in[0];
    float* out = (float*)d_out;

    const int blocks = HW / PIXB;   // 1152
    volume_render_v7_kernel<<<blocks, 256>>>(v, out);
}